// round 3
// baseline (speedup 1.0000x reference)
#include <cuda_runtime.h>
#include <math.h>

#define T_TOTAL 32768
#define NEXP    64
#define HDIM    1024
#define TILE_T  64
#define KC      32
#define NTHR    128
#define XPITCH  36          // floats; 16B-aligned rows

// Pre-transposed weights: Wt[k][e]
__device__ float g_Wt[HDIM * NEXP];

__global__ void transpose_w_kernel(const float* __restrict__ W) {
    int idx = blockIdx.x * blockDim.x + threadIdx.x;   // 65536 total
    int e = idx & (NEXP - 1);
    int k = idx >> 6;
    g_Wt[(size_t)k * NEXP + e] = W[(size_t)e * HDIM + k];
}

// packed f32x2 helpers
#define SPLAT2(d, f)   asm("mov.b64 %0, {%1, %1};" : "=l"(d) : "f"(f))
#define PACK2(d, a, b) asm("mov.b64 %0, {%1, %2};" : "=l"(d) : "f"(a), "f"(b))
#define UNPACK2(a, b, s) asm("mov.b64 {%0, %1}, %2;" : "=f"(a), "=f"(b) : "l"(s))
#define FMA2(acc, a, b) asm("fma.rn.f32x2 %0, %1, %2, %0;" : "+l"(acc) : "l"(a), "l"(b))

__device__ __forceinline__ bool better(float v, int i, float ov, int oi) {
    return (v > ov) || (v == ov && i < oi);
}

__global__ __launch_bounds__(NTHR, 5)
void moe_gate_kernel(const float* __restrict__ x,
                     float* __restrict__ out,
                     int out_size)
{
    __shared__ float xs[TILE_T][XPITCH];   // [tok][k] token-major
    __shared__ float ws[KC][NEXP];         // [k][e]  k-major

    const int tid = threadIdx.x;
    const int tx  = tid & 7;    // expert group: experts tx*8 .. tx*8+7
    const int ty  = tid >> 3;   // token group: tokens ty + 16*j, j=0..3

    const int tok_base = blockIdx.x * TILE_T;
    const float* xblk = x + (size_t)tok_base * HDIM;

    // accumulators: 4 tokens x 4 expert-pairs (f32x2)
    unsigned long long acc[4][4];
#pragma unroll
    for (int j = 0; j < 4; j++)
#pragma unroll
        for (int p = 0; p < 4; p++) acc[j][p] = 0ull;

    for (int k0 = 0; k0 < HDIM; k0 += KC) {
        // ---- load x tile: 64 tok x 32 k, float4, 4 per thread ----
#pragma unroll
        for (int i = 0; i < 4; i++) {
            int idx = i * NTHR + tid;
            int tok = idx >> 3, c = idx & 7;
            float4 v = *(const float4*)&xblk[(size_t)tok * HDIM + k0 + c * 4];
            *(float4*)&xs[tok][c * 4] = v;
        }
        // ---- load W tile: 32 k x 64 e, float4, 4 per thread (pre-transposed) ----
#pragma unroll
        for (int i = 0; i < 4; i++) {
            int idx = i * NTHR + tid;
            int r = idx >> 4, c4 = idx & 15;
            float4 v = *(const float4*)&g_Wt[(size_t)(k0 + r) * NEXP + c4 * 4];
            *(float4*)&ws[r][c4 * 4] = v;
        }
        __syncthreads();

#pragma unroll
        for (int kc4 = 0; kc4 < KC / 4; kc4++) {
            // b for 4 consecutive kk: 8 experts each -> 2 float4 per kk
            unsigned long long b2[4][4];
#pragma unroll
            for (int kk = 0; kk < 4; kk++) {
                float4 b0 = *(const float4*)&ws[kc4 * 4 + kk][tx * 8];
                float4 b1 = *(const float4*)&ws[kc4 * 4 + kk][tx * 8 + 4];
                PACK2(b2[kk][0], b0.x, b0.y);
                PACK2(b2[kk][1], b0.z, b0.w);
                PACK2(b2[kk][2], b1.x, b1.y);
                PACK2(b2[kk][3], b1.z, b1.w);
            }
#pragma unroll
            for (int j = 0; j < 4; j++) {
                float4 a = *(const float4*)&xs[ty + 16 * j][kc4 * 4];
                unsigned long long as;
                SPLAT2(as, a.x);
#pragma unroll
                for (int p = 0; p < 4; p++) FMA2(acc[j][p], as, b2[0][p]);
                SPLAT2(as, a.y);
#pragma unroll
                for (int p = 0; p < 4; p++) FMA2(acc[j][p], as, b2[1][p]);
                SPLAT2(as, a.z);
#pragma unroll
                for (int p = 0; p < 4; p++) FMA2(acc[j][p], as, b2[2][p]);
                SPLAT2(as, a.w);
#pragma unroll
                for (int p = 0; p < 4; p++) FMA2(acc[j][p], as, b2[3][p]);
            }
        }
        __syncthreads();
    }

    // ------------- fused softmax + top-2 epilogue (8-lane shuffle groups) ----
    float* oscore = out;
    float* oidx   = out + 2 * (size_t)T_TOTAL;

#pragma unroll
    for (int j = 0; j < 4; j++) {
        float l[8];
#pragma unroll
        for (int p = 0; p < 4; p++) UNPACK2(l[2 * p], l[2 * p + 1], acc[j][p]);

        // group max
        float m = l[0];
#pragma unroll
        for (int je = 1; je < 8; je++) m = fmaxf(m, l[je]);
#pragma unroll
        for (int off = 1; off < 8; off <<= 1)
            m = fmaxf(m, __shfl_xor_sync(0xffffffffu, m, off));

        // group sum of exp
        float s = 0.0f;
#pragma unroll
        for (int je = 0; je < 8; je++) s += expf(l[je] - m);
#pragma unroll
        for (int off = 1; off < 8; off <<= 1)
            s += __shfl_xor_sync(0xffffffffu, s, off);

        // local top-2 (ascending ids -> ties keep lower idx)
        float v1 = l[0], v2 = -INFINITY;
        int   i1 = tx * 8, i2 = NEXP;
#pragma unroll
        for (int je = 1; je < 8; je++) {
            float lv = l[je];
            int   e  = tx * 8 + je;
            if (lv > v1)      { v2 = v1; i2 = i1; v1 = lv; i1 = e; }
            else if (lv > v2) { v2 = lv; i2 = e; }
        }
        // merge across 8 lanes
#pragma unroll
        for (int off = 1; off < 8; off <<= 1) {
            float ov1 = __shfl_xor_sync(0xffffffffu, v1, off);
            int   oi1 = __shfl_xor_sync(0xffffffffu, i1, off);
            float ov2 = __shfl_xor_sync(0xffffffffu, v2, off);
            int   oi2 = __shfl_xor_sync(0xffffffffu, i2, off);
            if (better(ov1, oi1, v1, i1)) {
                if (better(v1, i1, ov2, oi2)) { v2 = v1; i2 = i1; }
                else                          { v2 = ov2; i2 = oi2; }
                v1 = ov1; i1 = oi1;
            } else {
                if (better(ov1, oi1, v2, i2)) { v2 = ov1; i2 = oi1; }
            }
        }

        if (tx == 0) {
            float p1 = expf(v1 - m) / s;
            float p2 = expf(v2 - m) / s;
            float e21 = expf(p2 - p1);
            float s1  = 1.0f / (1.0f + e21);
            float s2  = e21 * s1;
            int t = tok_base + ty + 16 * j;
            oscore[2 * t + 0] = s1;
            oscore[2 * t + 1] = s2;
            oidx[2 * t + 0]   = (float)i1;
            oidx[2 * t + 1]   = (float)i2;
        }
    }

    // tail (scalar zero output + anything past 4*T)
    if (blockIdx.x == 0 && tid < 32) {
        for (int p = 4 * T_TOTAL + tid; p < out_size; p += 32)
            out[p] = 0.0f;
    }
}

extern "C" void kernel_launch(void* const* d_in, const int* in_sizes, int n_in,
                              void* d_out, int out_size)
{
    const float* x = (const float*)d_in[0];
    const float* W = (const float*)d_in[1];
    float* out = (float*)d_out;

    transpose_w_kernel<<<256, 256>>>(W);
    moe_gate_kernel<<<T_TOTAL / TILE_T, NTHR>>>(x, out, out_size);
}

// round 4
// speedup vs baseline: 1.5975x; 1.5975x over previous
#include <cuda_runtime.h>
#include <math.h>

#define T_TOTAL 32768
#define NEXP    64
#define HDIM    1024
#define TILE_T  128
#define KC      16
#define NCHUNK  (HDIM / KC)   // 64
#define NTHR    128
#define XPITCH  20            // floats; 80B rows, 16B aligned, conflict-free
#define WPITCH  72            // floats; expert e at col e + 4*(e>>5)

// Pre-transposed + pre-swizzled weights: g_Wtp[k][WPITCH]
__device__ float g_Wtp[HDIM * WPITCH];

__global__ void transpose_w_kernel(const float* __restrict__ W) {
    int idx = blockIdx.x * blockDim.x + threadIdx.x;   // 65536 total
    int e = idx & (NEXP - 1);
    int k = idx >> 6;
    int col = e + 4 * (e >> 5);
    g_Wtp[(size_t)k * WPITCH + col] = W[(size_t)e * HDIM + k];
}

// packed f32x2 helpers
#define SPLAT2(d, f)   asm("mov.b64 %0, {%1, %1};" : "=l"(d) : "f"(f))
#define PACK2(d, a, b) asm("mov.b64 %0, {%1, %2};" : "=l"(d) : "f"(a), "f"(b))
#define UNPACK2(a, b, s) asm("mov.b64 {%0, %1}, %2;" : "=f"(a), "=f"(b) : "l"(s))
#define FMA2(acc, a, b) asm("fma.rn.f32x2 %0, %1, %2, %0;" : "+l"(acc) : "l"(a), "l"(b))

#define CP_ASYNC16(dst_u32, src) \
    asm volatile("cp.async.cg.shared.global [%0], [%1], 16;" :: "r"(dst_u32), "l"(src))
#define CP_COMMIT()  asm volatile("cp.async.commit_group;")
#define CP_WAIT1()   asm volatile("cp.async.wait_group 1;")

__device__ __forceinline__ bool better(float v, int i, float ov, int oi) {
    return (v > ov) || (v == ov && i < oi);
}

__global__ __launch_bounds__(NTHR, 2)
void moe_gate_kernel(const float* __restrict__ x,
                     float* __restrict__ out,
                     int out_size)
{
    __shared__ float xs[2][TILE_T][XPITCH];
    __shared__ float ws[2][KC][WPITCH];

    const int tid = threadIdx.x;
    const int tx  = tid & 7;    // expert group: experts tx*8 .. tx*8+7
    const int ty  = tid >> 3;   // token group: tokens ty + 16*j, j=0..7

    const int tok_base = blockIdx.x * TILE_T;
    const float* xblk = x + (size_t)tok_base * HDIM;

    // padded column base for this thread's 8 experts
    const int pc = tx * 8 + ((tx >= 4) ? 4 : 0);

    // ---- async copy of one K-chunk into buffer `buf` ----
    auto copy_chunk = [&](int c, int buf) {
        int k0 = c * KC;
        // x: 128 rows x 16 k = 512 x 16B chunks, 4 per thread
#pragma unroll
        for (int i = 0; i < 4; i++) {
            int idx = i * NTHR + tid;
            int row = idx >> 2, cc = idx & 3;
            unsigned d = (unsigned)__cvta_generic_to_shared(&xs[buf][row][cc * 4]);
            CP_ASYNC16(d, &xblk[(size_t)row * HDIM + k0 + cc * 4]);
        }
        // w: 16 rows x 18 x 16B chunks = 288, 3 per thread (guarded)
#pragma unroll
        for (int i = 0; i < 3; i++) {
            int idx = i * NTHR + tid;
            if (idx < KC * (WPITCH / 4)) {
                int row = idx / (WPITCH / 4), cc = idx % (WPITCH / 4);
                unsigned d = (unsigned)__cvta_generic_to_shared(&ws[buf][row][cc * 4]);
                CP_ASYNC16(d, &g_Wtp[(size_t)(k0 + row) * WPITCH + cc * 4]);
            }
        }
    };

    // accumulators: 8 tokens x 4 expert-pairs (f32x2)
    unsigned long long acc[8][4];
#pragma unroll
    for (int j = 0; j < 8; j++)
#pragma unroll
        for (int p = 0; p < 4; p++) acc[j][p] = 0ull;

    // prologue: prefetch chunks 0 and 1
    copy_chunk(0, 0); CP_COMMIT();
    copy_chunk(1, 1); CP_COMMIT();

    for (int c = 0; c < NCHUNK; c++) {
        const int buf = c & 1;
        CP_WAIT1();
        __syncthreads();

#pragma unroll
        for (int kc4 = 0; kc4 < KC / 4; kc4++) {
            unsigned long long b2[4][4];
#pragma unroll
            for (int kk = 0; kk < 4; kk++) {
                float4 b0 = *(const float4*)&ws[buf][kc4 * 4 + kk][pc];
                float4 b1 = *(const float4*)&ws[buf][kc4 * 4 + kk][pc + 4];
                PACK2(b2[kk][0], b0.x, b0.y);
                PACK2(b2[kk][1], b0.z, b0.w);
                PACK2(b2[kk][2], b1.x, b1.y);
                PACK2(b2[kk][3], b1.z, b1.w);
            }
#pragma unroll
            for (int j = 0; j < 8; j++) {
                float4 a = *(const float4*)&xs[buf][ty + 16 * j][kc4 * 4];
                unsigned long long as;
                SPLAT2(as, a.x);
#pragma unroll
                for (int p = 0; p < 4; p++) FMA2(acc[j][p], as, b2[0][p]);
                SPLAT2(as, a.y);
#pragma unroll
                for (int p = 0; p < 4; p++) FMA2(acc[j][p], as, b2[1][p]);
                SPLAT2(as, a.z);
#pragma unroll
                for (int p = 0; p < 4; p++) FMA2(acc[j][p], as, b2[2][p]);
                SPLAT2(as, a.w);
#pragma unroll
                for (int p = 0; p < 4; p++) FMA2(acc[j][p], as, b2[3][p]);
            }
        }
        __syncthreads();

        // issue prefetch for chunk c+2 into the buffer we just finished reading
        if (c + 2 < NCHUNK) copy_chunk(c + 2, buf);
        CP_COMMIT();   // always commit (empty groups keep wait_group semantics)
    }

    // ------------- fused softmax + top-2 epilogue (8-lane shuffle groups) ----
    float* oscore = out;
    float* oidx   = out + 2 * (size_t)T_TOTAL;

#pragma unroll
    for (int j = 0; j < 8; j++) {
        float l[8];
#pragma unroll
        for (int p = 0; p < 4; p++) UNPACK2(l[2 * p], l[2 * p + 1], acc[j][p]);

        // group max
        float m = l[0];
#pragma unroll
        for (int je = 1; je < 8; je++) m = fmaxf(m, l[je]);
#pragma unroll
        for (int off = 1; off < 8; off <<= 1)
            m = fmaxf(m, __shfl_xor_sync(0xffffffffu, m, off));

        // group sum of exp
        float s = 0.0f;
#pragma unroll
        for (int je = 0; je < 8; je++) s += expf(l[je] - m);
#pragma unroll
        for (int off = 1; off < 8; off <<= 1)
            s += __shfl_xor_sync(0xffffffffu, s, off);

        // local top-2 (ascending ids -> ties keep lower idx)
        float v1 = l[0], v2 = -INFINITY;
        int   i1 = tx * 8, i2 = NEXP;
#pragma unroll
        for (int je = 1; je < 8; je++) {
            float lv = l[je];
            int   e  = tx * 8 + je;
            if (lv > v1)      { v2 = v1; i2 = i1; v1 = lv; i1 = e; }
            else if (lv > v2) { v2 = lv; i2 = e; }
        }
        // merge across 8 lanes
#pragma unroll
        for (int off = 1; off < 8; off <<= 1) {
            float ov1 = __shfl_xor_sync(0xffffffffu, v1, off);
            int   oi1 = __shfl_xor_sync(0xffffffffu, i1, off);
            float ov2 = __shfl_xor_sync(0xffffffffu, v2, off);
            int   oi2 = __shfl_xor_sync(0xffffffffu, i2, off);
            if (better(ov1, oi1, v1, i1)) {
                if (better(v1, i1, ov2, oi2)) { v2 = v1; i2 = i1; }
                else                          { v2 = ov2; i2 = oi2; }
                v1 = ov1; i1 = oi1;
            } else {
                if (better(ov1, oi1, v2, i2)) { v2 = ov1; i2 = oi1; }
            }
        }

        if (tx == 0) {
            float p1 = expf(v1 - m) / s;
            float p2 = expf(v2 - m) / s;
            float e21 = expf(p2 - p1);
            float s1  = 1.0f / (1.0f + e21);
            float s2  = e21 * s1;
            int t = tok_base + ty + 16 * j;
            oscore[2 * t + 0] = s1;
            oscore[2 * t + 1] = s2;
            oidx[2 * t + 0]   = (float)i1;
            oidx[2 * t + 1]   = (float)i2;
        }
    }

    // tail (scalar zero output + anything past 4*T)
    if (blockIdx.x == 0 && tid < 32) {
        for (int p = 4 * T_TOTAL + tid; p < out_size; p += 32)
            out[p] = 0.0f;
    }
}

extern "C" void kernel_launch(void* const* d_in, const int* in_sizes, int n_in,
                              void* d_out, int out_size)
{
    const float* x = (const float*)d_in[0];
    const float* W = (const float*)d_in[1];
    float* out = (float*)d_out;

    transpose_w_kernel<<<256, 256>>>(W);
    moe_gate_kernel<<<T_TOTAL / TILE_T, NTHR>>>(x, out, out_size);
}

// round 5
// speedup vs baseline: 1.8299x; 1.1455x over previous
#include <cuda_runtime.h>
#include <math.h>

#define T_TOTAL 32768
#define NEXP    64
#define HDIM    1024
#define GRID    296           // 2 x 148 SMs -> exactly 2 CTAs per SM, one wave
#define NGROUP  7             // 7 token-groups of 16 -> up to 112 tokens per CTA
#define TROWS   112
#define KC      32
#define NCHUNK  (HDIM / KC)   // 32
#define NTHR    128
#define XPITCH  36            // 144B rows: bank-shift 4/row, conflict-free
#define WPITCH  72            // expert e at col e + 4*(e>>5), conflict-free

// Pre-transposed + pre-swizzled weights: g_Wtp[k][WPITCH]
__device__ float g_Wtp[HDIM * WPITCH];

__global__ void transpose_w_kernel(const float* __restrict__ W) {
    int idx = blockIdx.x * blockDim.x + threadIdx.x;   // 65536 total
    int e = idx & (NEXP - 1);
    int k = idx >> 6;
    int col = e + 4 * (e >> 5);
    g_Wtp[(size_t)k * WPITCH + col] = W[(size_t)e * HDIM + k];
}

// packed f32x2 helpers
#define SPLAT2(d, f)   asm("mov.b64 %0, {%1, %1};" : "=l"(d) : "f"(f))
#define PACK2(d, a, b) asm("mov.b64 %0, {%1, %2};" : "=l"(d) : "f"(a), "f"(b))
#define UNPACK2(a, b, s) asm("mov.b64 {%0, %1}, %2;" : "=f"(a), "=f"(b) : "l"(s))
#define FMA2(acc, a, b) asm("fma.rn.f32x2 %0, %1, %2, %0;" : "+l"(acc) : "l"(a), "l"(b))

#define CP_ASYNC16(dst_u32, src) \
    asm volatile("cp.async.cg.shared.global [%0], [%1], 16;" :: "r"(dst_u32), "l"(src))
#define CP_COMMIT()  asm volatile("cp.async.commit_group;")
#define CP_WAIT1()   asm volatile("cp.async.wait_group 1;")

__device__ __forceinline__ bool better(float v, int i, float ov, int oi) {
    return (v > ov) || (v == ov && i < oi);
}

// dynamic smem layout (floats):
//   xs[2][TROWS][XPITCH]  = 2*112*36 = 8064
//   ws[2][KC][WPITCH]     = 2*32*72  = 4608
#define XS_F      (TROWS * XPITCH)
#define WS_F      (KC * WPITCH)
#define SMEM_FLOATS (2 * XS_F + 2 * WS_F)

__global__ __launch_bounds__(NTHR, 2)
void moe_gate_kernel(const float* __restrict__ x,
                     float* __restrict__ out,
                     int out_size)
{
    extern __shared__ float smem[];
    float* xs0 = smem;                       // [2][TROWS][XPITCH]
    float* ws0 = smem + 2 * XS_F;            // [2][KC][WPITCH]

    const int tid = threadIdx.x;
    const int tx  = tid & 7;    // expert group: experts tx*8 .. tx*8+7
    const int ty  = tid >> 3;   // token group: token = start + ty + 16*j

    // token range for this CTA (110 or 111 tokens)
    const int start = (int)(((long long)blockIdx.x * T_TOTAL) / GRID);
    const int end   = (int)(((long long)(blockIdx.x + 1) * T_TOTAL) / GRID);
    const int count = end - start;
    const float* xblk = x + (size_t)start * HDIM;

    // padded column base for this thread's 8 experts
    const int pc = tx * 8 + ((tx >= 4) ? 4 : 0);

    auto copy_chunk = [&](int c, int buf) {
        int k0 = c * KC;
        float* xsb = xs0 + buf * XS_F;
        float* wsb = ws0 + buf * WS_F;
        // x: 112 rows x 8 float4 = 896 ops, 7 per thread (rows >= count clamped)
#pragma unroll
        for (int i = 0; i < 7; i++) {
            int idx = i * NTHR + tid;
            int row = idx >> 3, cc = idx & 7;
            int gr = (row < count) ? row : 0;
            unsigned d = (unsigned)__cvta_generic_to_shared(&xsb[row * XPITCH + cc * 4]);
            CP_ASYNC16(d, &xblk[(size_t)gr * HDIM + k0 + cc * 4]);
        }
        // w: 32 rows x 18 float4 = 576 ops, 4.5 per thread
#pragma unroll
        for (int i = 0; i < 5; i++) {
            int idx = i * NTHR + tid;
            if (idx < KC * (WPITCH / 4)) {
                int row = idx / (WPITCH / 4), cc = idx % (WPITCH / 4);
                unsigned d = (unsigned)__cvta_generic_to_shared(&wsb[row * WPITCH + cc * 4]);
                CP_ASYNC16(d, &g_Wtp[(size_t)(k0 + row) * WPITCH + cc * 4]);
            }
        }
    };

    // accumulators: 7 token-groups x 4 expert-pairs (f32x2)
    unsigned long long acc[NGROUP][4];
#pragma unroll
    for (int j = 0; j < NGROUP; j++)
#pragma unroll
        for (int p = 0; p < 4; p++) acc[j][p] = 0ull;

    copy_chunk(0, 0); CP_COMMIT();
    copy_chunk(1, 1); CP_COMMIT();

    for (int c = 0; c < NCHUNK; c++) {
        const int buf = c & 1;
        const float* xsb = xs0 + buf * XS_F;
        const float* wsb = ws0 + buf * WS_F;
        CP_WAIT1();
        __syncthreads();

#pragma unroll
        for (int kc4 = 0; kc4 < KC / 4; kc4++) {
            unsigned long long b2[4][4];
#pragma unroll
            for (int kk = 0; kk < 4; kk++) {
                float4 b0 = *(const float4*)&wsb[(kc4 * 4 + kk) * WPITCH + pc];
                float4 b1 = *(const float4*)&wsb[(kc4 * 4 + kk) * WPITCH + pc + 4];
                PACK2(b2[kk][0], b0.x, b0.y);
                PACK2(b2[kk][1], b0.z, b0.w);
                PACK2(b2[kk][2], b1.x, b1.y);
                PACK2(b2[kk][3], b1.z, b1.w);
            }
#pragma unroll
            for (int j = 0; j < NGROUP; j++) {
                float4 a = *(const float4*)&xsb[(ty + 16 * j) * XPITCH + kc4 * 4];
                unsigned long long as;
                SPLAT2(as, a.x);
#pragma unroll
                for (int p = 0; p < 4; p++) FMA2(acc[j][p], as, b2[0][p]);
                SPLAT2(as, a.y);
#pragma unroll
                for (int p = 0; p < 4; p++) FMA2(acc[j][p], as, b2[1][p]);
                SPLAT2(as, a.z);
#pragma unroll
                for (int p = 0; p < 4; p++) FMA2(acc[j][p], as, b2[2][p]);
                SPLAT2(as, a.w);
#pragma unroll
                for (int p = 0; p < 4; p++) FMA2(acc[j][p], as, b2[3][p]);
            }
        }
        __syncthreads();

        if (c + 2 < NCHUNK) copy_chunk(c + 2, buf);
        CP_COMMIT();
    }

    // ------------- fused softmax + top-2 epilogue (8-lane shuffle groups) ----
    float* oscore = out;
    float* oidx   = out + 2 * (size_t)T_TOTAL;

#pragma unroll
    for (int j = 0; j < NGROUP; j++) {
        if (ty + 16 * j >= count) break;   // uniform across the 8 lanes of a group
        float l[8];
#pragma unroll
        for (int p = 0; p < 4; p++) UNPACK2(l[2 * p], l[2 * p + 1], acc[j][p]);

        // group max
        float m = l[0];
#pragma unroll
        for (int je = 1; je < 8; je++) m = fmaxf(m, l[je]);
#pragma unroll
        for (int off = 1; off < 8; off <<= 1)
            m = fmaxf(m, __shfl_xor_sync(0xffffffffu, m, off));

        // group sum of exp
        float s = 0.0f;
#pragma unroll
        for (int je = 0; je < 8; je++) s += expf(l[je] - m);
#pragma unroll
        for (int off = 1; off < 8; off <<= 1)
            s += __shfl_xor_sync(0xffffffffu, s, off);

        // local top-2 (ascending ids -> ties keep lower idx)
        float v1 = l[0], v2 = -INFINITY;
        int   i1 = tx * 8, i2 = NEXP;
#pragma unroll
        for (int je = 1; je < 8; je++) {
            float lv = l[je];
            int   e  = tx * 8 + je;
            if (lv > v1)      { v2 = v1; i2 = i1; v1 = lv; i1 = e; }
            else if (lv > v2) { v2 = lv; i2 = e; }
        }
        // merge across 8 lanes
#pragma unroll
        for (int off = 1; off < 8; off <<= 1) {
            float ov1 = __shfl_xor_sync(0xffffffffu, v1, off);
            int   oi1 = __shfl_xor_sync(0xffffffffu, i1, off);
            float ov2 = __shfl_xor_sync(0xffffffffu, v2, off);
            int   oi2 = __shfl_xor_sync(0xffffffffu, i2, off);
            if (better(ov1, oi1, v1, i1)) {
                if (better(v1, i1, ov2, oi2)) { v2 = v1; i2 = i1; }
                else                          { v2 = ov2; i2 = oi2; }
                v1 = ov1; i1 = oi1;
            } else {
                if (better(ov1, oi1, v2, i2)) { v2 = ov1; i2 = oi1; }
            }
        }

        if (tx == 0) {
            float p1 = expf(v1 - m) / s;
            float p2 = expf(v2 - m) / s;
            float e21 = expf(p2 - p1);
            float s1  = 1.0f / (1.0f + e21);
            float s2  = e21 * s1;
            int t = start + ty + 16 * j;
            oscore[2 * t + 0] = s1;
            oscore[2 * t + 1] = s2;
            oidx[2 * t + 0]   = (float)i1;
            oidx[2 * t + 1]   = (float)i2;
        }
    }

    // tail (scalar zero output + anything past 4*T)
    if (blockIdx.x == 0 && tid < 32) {
        for (int p = 4 * T_TOTAL + tid; p < out_size; p += 32)
            out[p] = 0.0f;
    }
}

extern "C" void kernel_launch(void* const* d_in, const int* in_sizes, int n_in,
                              void* d_out, int out_size)
{
    const float* x = (const float*)d_in[0];
    const float* W = (const float*)d_in[1];
    float* out = (float*)d_out;

    static bool attr_set = false;
    if (!attr_set) {
        cudaFuncSetAttribute(moe_gate_kernel,
                             cudaFuncAttributeMaxDynamicSharedMemorySize,
                             SMEM_FLOATS * (int)sizeof(float));
        attr_set = true;
    }

    transpose_w_kernel<<<256, 256>>>(W);
    moe_gate_kernel<<<GRID, NTHR, SMEM_FLOATS * sizeof(float)>>>(x, out, out_size);
}